// round 1
// baseline (speedup 1.0000x reference)
#include <cuda_runtime.h>
#include <cuda_bf16.h>
#include <mma.h>

using namespace nvcuda;

typedef __nv_bfloat16 bf16;

#define HID  1024
#define G4   4096
#define BAT  64
#define TT   100
#define INS  171
#define KIN  176   // padded 171 -> multiple of 16
#define NDEC 192   // padded decoder rows (171 -> 192 = 6*32)
#define BN   32    // gate-columns per block tile

// ---------------- persistent device buffers (no allocation allowed) ----------------
__device__ bf16  g_wih1_h[G4 * KIN];
__device__ bf16  g_wih1_l[G4 * KIN];
__device__ bf16  g_wihA_h[2][G4 * HID];   // layers 2,3 input weights
__device__ bf16  g_wihA_l[2][G4 * HID];
__device__ bf16  g_whh_h[3][G4 * HID];
__device__ bf16  g_whh_l[3][G4 * HID];
__device__ bf16  g_dec_h[NDEC * HID];
__device__ bf16  g_dec_l[NDEC * HID];
__device__ float g_bias[3][G4];
__device__ float g_dbias[NDEC];
__device__ bf16  g_fr_h[TT * BAT * KIN];
__device__ bf16  g_fr_l[TT * BAT * KIN];
__device__ bf16  g_h_h[2][3][BAT * HID];  // double buffered: [t parity][layer]
__device__ bf16  g_h_l[2][3][BAT * HID];
__device__ float g_c[3][BAT * HID];
__device__ bf16  g_po_h[BAT * KIN];       // prev decoder output (split), padded
__device__ bf16  g_po_l[BAT * KIN];

__device__ __forceinline__ void split2(float v, bf16& hi, bf16& lo) {
    hi = __float2bfloat16(v);
    lo = __float2bfloat16(v - __bfloat162float(hi));
}

// ---------------- prep kernels ----------------

// Reorder LSTM weight rows (g*H + j) -> (j*4 + g), pad K, split to bf16 hi/lo.
// slot: 0 = wih1 (Ks=INS, Kp=KIN), 1/2 = wihA[0/1], 3/4/5 = whh[0/1/2]
__global__ void prep_reorder(const float* __restrict__ src, int slot) {
    bf16 *dh, *dl;
    int Ks, Kp;
    if (slot == 0)      { dh = g_wih1_h;        dl = g_wih1_l;        Ks = INS; Kp = KIN; }
    else if (slot <= 2) { dh = g_wihA_h[slot-1]; dl = g_wihA_l[slot-1]; Ks = HID; Kp = HID; }
    else                { dh = g_whh_h[slot-3];  dl = g_whh_l[slot-3];  Ks = HID; Kp = HID; }
    int n = G4 * Kp;
    for (int i = blockIdx.x * blockDim.x + threadIdx.x; i < n; i += gridDim.x * blockDim.x) {
        int r = i / Kp, k = i - r * Kp;
        int j = r >> 2, g = r & 3;
        float v = (k < Ks) ? src[(g * HID + j) * Ks + k] : 0.0f;
        split2(v, dh[i], dl[i]);
    }
}

__global__ void prep_dec(const float* __restrict__ src) {
    int n = NDEC * HID;
    for (int i = blockIdx.x * blockDim.x + threadIdx.x; i < n; i += gridDim.x * blockDim.x) {
        int r = i / HID, k = i - r * HID;
        float v = (r < INS) ? src[r * HID + k] : 0.0f;
        split2(v, g_dec_h[i], g_dec_l[i]);
    }
}

__global__ void prep_bias(const float* __restrict__ bi, const float* __restrict__ bh, int layer) {
    for (int i = blockIdx.x * blockDim.x + threadIdx.x; i < G4; i += gridDim.x * blockDim.x) {
        int j = i >> 2, g = i & 3;
        g_bias[layer][i] = bi[g * HID + j] + bh[g * HID + j];
    }
}

__global__ void prep_dbias(const float* __restrict__ db) {
    for (int i = blockIdx.x * blockDim.x + threadIdx.x; i < NDEC; i += gridDim.x * blockDim.x)
        g_dbias[i] = (i < INS) ? db[i] : 0.0f;
}

// real_seq [B][T][INS] -> g_fr [T][B][KIN] split, zero-padded
__global__ void prep_frames(const float* __restrict__ rs) {
    int n = TT * BAT * KIN;
    for (int i = blockIdx.x * blockDim.x + threadIdx.x; i < n; i += gridDim.x * blockDim.x) {
        int t   = i / (BAT * KIN);
        int rem = i - t * (BAT * KIN);
        int b = rem / KIN, k = rem - b * KIN;
        float v = (k < INS) ? rs[(b * TT + t) * INS + k] : 0.0f;
        split2(v, g_fr_h[i], g_fr_l[i]);
    }
}

__global__ void prep_zero() {
    int n1 = 2 * 3 * BAT * HID;
    for (int i = blockIdx.x * blockDim.x + threadIdx.x; i < n1; i += gridDim.x * blockDim.x) {
        ((bf16*)g_h_h)[i] = __float2bfloat16(0.0f);
        ((bf16*)g_h_l)[i] = __float2bfloat16(0.0f);
    }
    int n2 = 3 * BAT * HID;
    for (int i = blockIdx.x * blockDim.x + threadIdx.x; i < n2; i += gridDim.x * blockDim.x)
        ((float*)g_c)[i] = 0.0f;
    int n3 = BAT * KIN;
    for (int i = blockIdx.x * blockDim.x + threadIdx.x; i < n3; i += gridDim.x * blockDim.x) {
        g_po_h[i] = __float2bfloat16(0.0f);
        g_po_l[i] = __float2bfloat16(0.0f);
    }
}

// ---------------- per-step LSTM layer (GEMM + fused cell update) ----------------
// grid = G4/BN = 128 blocks, 256 threads (8 warps: 4 m-warps x 2 n-warps)
__global__ __launch_bounds__(256) void lstm_step(int layer, int t, int use_frame) {
    int cur = t & 1;        // recurrent-input buffer
    int nxt = cur ^ 1;      // output buffer (also holds lower layer's fresh h)

    const bf16 *xh, *xl, *wxh, *wxl;
    int Kx;
    if (layer == 0) {
        Kx = KIN;
        if (use_frame) { xh = g_fr_h + t * BAT * KIN; xl = g_fr_l + t * BAT * KIN; }
        else           { xh = g_po_h;                 xl = g_po_l; }
        wxh = g_wih1_h; wxl = g_wih1_l;
    } else {
        Kx = HID;
        xh = g_h_h[nxt][layer - 1]; xl = g_h_l[nxt][layer - 1];
        wxh = g_wihA_h[layer - 1];  wxl = g_wihA_l[layer - 1];
    }
    const bf16 *hh  = g_h_h[cur][layer], *hl  = g_h_l[cur][layer];
    const bf16 *whh = g_whh_h[layer],    *whl = g_whh_l[layer];

    int n0   = blockIdx.x * BN;
    int warp = threadIdx.x >> 5;
    int wm   = warp & 3;    // batch rows wm*16 .. wm*16+15
    int wn   = warp >> 2;   // gate cols n0 + wn*16 ..

    wmma::fragment<wmma::accumulator, 16, 16, 16, float> acc;
    wmma::fill_fragment(acc, 0.0f);
    wmma::fragment<wmma::matrix_a, 16, 16, 16, bf16, wmma::row_major> Ah, Al;
    wmma::fragment<wmma::matrix_b, 16, 16, 16, bf16, wmma::col_major> Bh, Bl;

    {   // x path
        const bf16* ar_h = xh + wm * 16 * Kx;
        const bf16* ar_l = xl + wm * 16 * Kx;
        const bf16* bc_h = wxh + (n0 + wn * 16) * Kx;
        const bf16* bc_l = wxl + (n0 + wn * 16) * Kx;
        for (int kc = 0; kc < Kx; kc += 16) {
            wmma::load_matrix_sync(Ah, ar_h + kc, Kx);
            wmma::load_matrix_sync(Al, ar_l + kc, Kx);
            wmma::load_matrix_sync(Bh, bc_h + kc, Kx);
            wmma::load_matrix_sync(Bl, bc_l + kc, Kx);
            wmma::mma_sync(acc, Ah, Bh, acc);
            wmma::mma_sync(acc, Ah, Bl, acc);
            wmma::mma_sync(acc, Al, Bh, acc);
        }
    }
    {   // recurrent path
        const bf16* ar_h = hh + wm * 16 * HID;
        const bf16* ar_l = hl + wm * 16 * HID;
        const bf16* bc_h = whh + (n0 + wn * 16) * HID;
        const bf16* bc_l = whl + (n0 + wn * 16) * HID;
        for (int kc = 0; kc < HID; kc += 16) {
            wmma::load_matrix_sync(Ah, ar_h + kc, HID);
            wmma::load_matrix_sync(Al, ar_l + kc, HID);
            wmma::load_matrix_sync(Bh, bc_h + kc, HID);
            wmma::load_matrix_sync(Bl, bc_l + kc, HID);
            wmma::mma_sync(acc, Ah, Bh, acc);
            wmma::mma_sync(acc, Ah, Bl, acc);
            wmma::mma_sync(acc, Al, Bh, acc);
        }
    }

    __shared__ float cs[BAT][BN];
    wmma::store_matrix_sync(&cs[wm * 16][wn * 16], acc, BN, wmma::mem_row_major);
    __syncthreads();

    const float* bias = g_bias[layer];
    float* cst = g_c[layer];
    bf16 *oh = g_h_h[nxt][layer], *ol = g_h_l[nxt][layer];
    int j0 = n0 >> 2;   // 8 hidden units per block
    for (int p = threadIdx.x; p < BAT * (BN / 4); p += blockDim.x) {
        int b = p >> 3;
        int u = p & 7;
        float gi = cs[b][4 * u + 0] + bias[n0 + 4 * u + 0];
        float gf = cs[b][4 * u + 1] + bias[n0 + 4 * u + 1];
        float gg = cs[b][4 * u + 2] + bias[n0 + 4 * u + 2];
        float go = cs[b][4 * u + 3] + bias[n0 + 4 * u + 3];
        gi = 1.0f / (1.0f + expf(-gi));
        gf = 1.0f / (1.0f + expf(-gf));
        gg = tanhf(gg);
        go = 1.0f / (1.0f + expf(-go));
        int j = j0 + u;
        float cv = gf * cst[b * HID + j] + gi * gg;
        cst[b * HID + j] = cv;
        float hv = go * tanhf(cv);
        split2(hv, oh[b * HID + j], ol[b * HID + j]);
    }
}

// ---------------- decoder: out = h2 @ dec_w^T + dec_b ----------------
// grid = NDEC/BN = 6 blocks
__global__ __launch_bounds__(256) void dec_step(int t, float* __restrict__ out) {
    int nxt = (t & 1) ^ 1;
    const bf16 *ahp = g_h_h[nxt][2], *alp = g_h_l[nxt][2];

    int n0   = blockIdx.x * BN;
    int warp = threadIdx.x >> 5;
    int wm   = warp & 3;
    int wn   = warp >> 2;

    wmma::fragment<wmma::accumulator, 16, 16, 16, float> acc;
    wmma::fill_fragment(acc, 0.0f);
    wmma::fragment<wmma::matrix_a, 16, 16, 16, bf16, wmma::row_major> Ah, Al;
    wmma::fragment<wmma::matrix_b, 16, 16, 16, bf16, wmma::col_major> Bh, Bl;

    const bf16* ar_h = ahp + wm * 16 * HID;
    const bf16* ar_l = alp + wm * 16 * HID;
    const bf16* bc_h = g_dec_h + (n0 + wn * 16) * HID;
    const bf16* bc_l = g_dec_l + (n0 + wn * 16) * HID;
    for (int kc = 0; kc < HID; kc += 16) {
        wmma::load_matrix_sync(Ah, ar_h + kc, HID);
        wmma::load_matrix_sync(Al, ar_l + kc, HID);
        wmma::load_matrix_sync(Bh, bc_h + kc, HID);
        wmma::load_matrix_sync(Bl, bc_l + kc, HID);
        wmma::mma_sync(acc, Ah, Bh, acc);
        wmma::mma_sync(acc, Ah, Bl, acc);
        wmma::mma_sync(acc, Al, Bh, acc);
    }

    __shared__ float cs[BAT][BN];
    wmma::store_matrix_sync(&cs[wm * 16][wn * 16], acc, BN, wmma::mem_row_major);
    __syncthreads();

    for (int p = threadIdx.x; p < BAT * BN; p += blockDim.x) {
        int b = p >> 5;
        int u = p & 31;
        int col = n0 + u;
        if (col < INS) {
            float v = cs[b][u] + g_dbias[col];
            out[b * (TT * INS) + t * INS + col] = v;
            split2(v, g_po_h[b * KIN + col], g_po_l[b * KIN + col]);
        }
    }
}

// ---------------- launch ----------------
extern "C" void kernel_launch(void* const* d_in, const int* in_sizes, int n_in,
                              void* d_out, int out_size) {
    const float* rs    = (const float*)d_in[0];
    const float* wih1  = (const float*)d_in[1];
    const float* whh1  = (const float*)d_in[2];
    const float* bih1  = (const float*)d_in[3];
    const float* bhh1  = (const float*)d_in[4];
    const float* wih2  = (const float*)d_in[5];
    const float* whh2  = (const float*)d_in[6];
    const float* bih2  = (const float*)d_in[7];
    const float* bhh2  = (const float*)d_in[8];
    const float* wih3  = (const float*)d_in[9];
    const float* whh3  = (const float*)d_in[10];
    const float* bih3  = (const float*)d_in[11];
    const float* bhh3  = (const float*)d_in[12];
    const float* decw  = (const float*)d_in[13];
    const float* decb  = (const float*)d_in[14];
    float* out = (float*)d_out;

    // weight / input preparation (every launch; deterministic)
    prep_reorder<<<1024, 256>>>(wih1, 0);
    prep_reorder<<<1024, 256>>>(wih2, 1);
    prep_reorder<<<1024, 256>>>(wih3, 2);
    prep_reorder<<<1024, 256>>>(whh1, 3);
    prep_reorder<<<1024, 256>>>(whh2, 4);
    prep_reorder<<<1024, 256>>>(whh3, 5);
    prep_dec<<<512, 256>>>(decw);
    prep_bias<<<16, 256>>>(bih1, bhh1, 0);
    prep_bias<<<16, 256>>>(bih2, bhh2, 1);
    prep_bias<<<16, 256>>>(bih3, bhh3, 2);
    prep_dbias<<<1, 256>>>(decb);
    prep_frames<<<1024, 256>>>(rs);
    prep_zero<<<512, 256>>>();

    for (int t = 0; t < TT; t++) {
        int use_frame = ((t % 10) < 5) ? 1 : 0;
        lstm_step<<<G4 / BN, 256>>>(0, t, use_frame);
        lstm_step<<<G4 / BN, 256>>>(1, t, use_frame);
        lstm_step<<<G4 / BN, 256>>>(2, t, use_frame);
        dec_step<<<NDEC / BN, 256>>>(t, out);
    }
}

// round 3
// speedup vs baseline: 3.1012x; 3.1012x over previous
#include <cuda_runtime.h>
#include <cuda_bf16.h>
#include <mma.h>
#include <cstdint>

using namespace nvcuda;
typedef __nv_bfloat16 bf16;

#define HID   1024
#define G4    4096
#define BAT   64
#define TT    100
#define INS   171
#define KX0   192          // padded input width (multiple of 64)
#define KCAT0 (KX0 + HID)  // 1216
#define KCAT12 (2 * HID)   // 2048
#define NDEC  192
#define SMSA  72           // smem row stride (bf16 elems) -> 144B, conflict-free LDSM

// ---------------- persistent device buffers ----------------
__device__ bf16  g_w_h[(KCAT0 + 2 * KCAT12) * G4];
__device__ bf16  g_w_l[(KCAT0 + 2 * KCAT12) * G4];
__device__ bf16  g_dec_h[NDEC * HID];
__device__ bf16  g_dec_l[NDEC * HID];
__device__ float g_bias[3][G4];
__device__ float g_dbias[NDEC];
__device__ bf16  g_fr_h[TT * BAT * KX0];
__device__ bf16  g_fr_l[TT * BAT * KX0];
__device__ bf16  g_h_h[2][3][BAT * HID];
__device__ bf16  g_h_l[2][3][BAT * HID];
__device__ float g_c[3][BAT * HID];
__device__ bf16  g_po_h[BAT * KX0];
__device__ bf16  g_po_l[BAT * KX0];

__device__ __forceinline__ void split2(float v, bf16& hi, bf16& lo) {
    hi = __float2bfloat16(v);
    lo = __float2bfloat16(v - __bfloat162float(hi));
}

__device__ __forceinline__ void cp16(void* dst, const void* src) {
    unsigned int d = (unsigned int)__cvta_generic_to_shared(dst);
    asm volatile("cp.async.cg.shared.global [%0], [%1], 16;" :: "r"(d), "l"(src));
}
#define CP_COMMIT() asm volatile("cp.async.commit_group;")
#define CP_WAIT1()  asm volatile("cp.async.wait_group 1;")

// ---------------- prep kernels ----------------

// Build concatenated, gate-interleaved, split weights: W[layer][col][k], col = j*4+g,
// k in [0,KxPad) from wx (zero-padded beyond KxSrc), then HID rows from wh.
__global__ void prep_w(const float* __restrict__ wx, const float* __restrict__ wh_,
                       int layer, int KxPad, int KxSrc) {
    int KCAT = KxPad + HID;
    size_t off = (layer == 0) ? 0 : (size_t)KCAT0 * G4 + (size_t)(layer - 1) * KCAT12 * G4;
    bf16* dh = g_w_h + off;
    bf16* dl = g_w_l + off;
    int n = G4 * KCAT;
    for (int i = blockIdx.x * blockDim.x + threadIdx.x; i < n; i += gridDim.x * blockDim.x) {
        int col = i / KCAT, k = i - col * KCAT;
        int j = col >> 2, g = col & 3;
        float v;
        if (k < KxPad) v = (k < KxSrc) ? wx[(g * HID + j) * KxSrc + k] : 0.0f;
        else           v = wh_[(g * HID + j) * HID + (k - KxPad)];
        split2(v, dh[i], dl[i]);
    }
}

__global__ void prep_dec(const float* __restrict__ src) {
    int n = NDEC * HID;
    for (int i = blockIdx.x * blockDim.x + threadIdx.x; i < n; i += gridDim.x * blockDim.x) {
        int r = i / HID, k = i - r * HID;
        float v = (r < INS) ? src[r * HID + k] : 0.0f;
        split2(v, g_dec_h[i], g_dec_l[i]);
    }
}

__global__ void prep_bias(const float* __restrict__ bi, const float* __restrict__ bh, int layer) {
    for (int i = blockIdx.x * blockDim.x + threadIdx.x; i < G4; i += gridDim.x * blockDim.x) {
        int j = i >> 2, g = i & 3;
        g_bias[layer][i] = bi[g * HID + j] + bh[g * HID + j];
    }
}

__global__ void prep_dbias(const float* __restrict__ db) {
    for (int i = blockIdx.x * blockDim.x + threadIdx.x; i < NDEC; i += gridDim.x * blockDim.x)
        g_dbias[i] = (i < INS) ? db[i] : 0.0f;
}

// real_seq [B][T][INS] -> g_fr [T][B][KX0] split, zero-padded
__global__ void prep_frames(const float* __restrict__ rs) {
    int n = TT * BAT * KX0;
    for (int i = blockIdx.x * blockDim.x + threadIdx.x; i < n; i += gridDim.x * blockDim.x) {
        int t   = i / (BAT * KX0);
        int rem = i - t * (BAT * KX0);
        int b = rem / KX0, k = rem - b * KX0;
        float v = (k < INS) ? rs[(b * TT + t) * INS + k] : 0.0f;
        split2(v, g_fr_h[i], g_fr_l[i]);
    }
}

__global__ void prep_zero() {
    int n1 = 2 * 3 * BAT * HID;
    for (int i = blockIdx.x * blockDim.x + threadIdx.x; i < n1; i += gridDim.x * blockDim.x) {
        ((bf16*)g_h_h)[i] = __float2bfloat16(0.0f);
        ((bf16*)g_h_l)[i] = __float2bfloat16(0.0f);
    }
    int n2 = 3 * BAT * HID;
    for (int i = blockIdx.x * blockDim.x + threadIdx.x; i < n2; i += gridDim.x * blockDim.x)
        ((float*)g_c)[i] = 0.0f;
    int n3 = BAT * KX0;
    for (int i = blockIdx.x * blockDim.x + threadIdx.x; i < n3; i += gridDim.x * blockDim.x) {
        g_po_h[i] = __float2bfloat16(0.0f);
        g_po_l[i] = __float2bfloat16(0.0f);
    }
}

// ---------------- per-step LSTM layer: smem-pipelined GEMM + fused cell ----------------
// grid = 128 blocks (32 gate cols each), 256 threads (8 warps: 4m x 2n)
// smem: A[2][64][72] h+l, B[2][32][72] h+l, cs[64][32]
#define SMEM_BYTES ((2*64*SMSA + 2*32*SMSA) * 2 * 2 + 64 * 32 * 4)

__global__ __launch_bounds__(256) void lstm_step(int layer, int t, int use_frame) {
    extern __shared__ char sraw[];
    bf16* sA_h = (bf16*)sraw;                      // [2][64][SMSA]
    bf16* sA_l = sA_h + 2 * 64 * SMSA;
    bf16* sB_h = sA_l + 2 * 64 * SMSA;             // [2][32][SMSA]
    bf16* sB_l = sB_h + 2 * 32 * SMSA;
    float (*cs)[32] = (float (*)[32])(sB_l + 2 * 32 * SMSA);

    int cur = t & 1, nxt = cur ^ 1;
    int KCAT, K0, ld0;
    const bf16 *a0h, *a0l, *a1h, *a1l, *wh, *wl;
    if (layer == 0) {
        KCAT = KCAT0; K0 = KX0; ld0 = KX0;
        if (use_frame) { a0h = g_fr_h + t * BAT * KX0; a0l = g_fr_l + t * BAT * KX0; }
        else           { a0h = g_po_h;                 a0l = g_po_l; }
        a1h = g_h_h[cur][0]; a1l = g_h_l[cur][0];
        wh = g_w_h; wl = g_w_l;
    } else {
        KCAT = KCAT12; K0 = HID; ld0 = HID;
        a0h = g_h_h[nxt][layer - 1]; a0l = g_h_l[nxt][layer - 1];
        a1h = g_h_h[cur][layer];     a1l = g_h_l[cur][layer];
        size_t off = (size_t)KCAT0 * G4 + (size_t)(layer - 1) * KCAT12 * G4;
        wh = g_w_h + off; wl = g_w_l + off;
    }
    int NCH = KCAT / 64;
    int n0  = blockIdx.x * 32;
    int tid = threadIdx.x;

    auto issue = [&](int c, int buf) {
        int k0 = c * 64;
        const bf16 *sh, *sl; int ld, ko;
        if (k0 < K0) { sh = a0h; sl = a0l; ld = ld0; ko = k0; }
        else         { sh = a1h; sl = a1l; ld = HID; ko = k0 - K0; }
        bf16* dAh = sA_h + buf * 64 * SMSA;
        bf16* dAl = sA_l + buf * 64 * SMSA;
        #pragma unroll
        for (int i = tid; i < 512; i += 256) {
            int r = i >> 3, s = (i & 7) * 8;
            cp16(dAh + r * SMSA + s, sh + r * ld + ko + s);
            cp16(dAl + r * SMSA + s, sl + r * ld + ko + s);
        }
        {
            int r = tid >> 3, s = (tid & 7) * 8;   // 256 segs exactly
            bf16* dBh = sB_h + buf * 32 * SMSA;
            bf16* dBl = sB_l + buf * 32 * SMSA;
            int boff = (n0 + r) * KCAT + k0 + s;
            cp16(dBh + r * SMSA + s, wh + boff);
            cp16(dBl + r * SMSA + s, wl + boff);
        }
    };

    int warp = tid >> 5;
    int wm = warp & 3;     // batch rows wm*16..
    int wn = warp >> 2;    // gate cols n0 + wn*16..

    wmma::fragment<wmma::accumulator, 16, 16, 16, float> acc0, acc1;
    wmma::fill_fragment(acc0, 0.0f);
    wmma::fill_fragment(acc1, 0.0f);
    wmma::fragment<wmma::matrix_a, 16, 16, 16, bf16, wmma::row_major> Ah, Al;
    wmma::fragment<wmma::matrix_b, 16, 16, 16, bf16, wmma::col_major> Bh, Bl;

    issue(0, 0); CP_COMMIT();
    issue(1, 1); CP_COMMIT();

    for (int c = 0; c < NCH; c++) {
        CP_WAIT1();
        __syncthreads();
        int buf = c & 1;
        const bf16* pAh = sA_h + buf * 64 * SMSA + wm * 16 * SMSA;
        const bf16* pAl = sA_l + buf * 64 * SMSA + wm * 16 * SMSA;
        const bf16* pBh = sB_h + buf * 32 * SMSA + wn * 16 * SMSA;
        const bf16* pBl = sB_l + buf * 32 * SMSA + wn * 16 * SMSA;
        #pragma unroll
        for (int kk = 0; kk < 4; kk++) {
            wmma::load_matrix_sync(Ah, pAh + kk * 16, SMSA);
            wmma::load_matrix_sync(Al, pAl + kk * 16, SMSA);
            wmma::load_matrix_sync(Bh, pBh + kk * 16, SMSA);
            wmma::load_matrix_sync(Bl, pBl + kk * 16, SMSA);
            wmma::mma_sync(acc0, Ah, Bh, acc0);
            wmma::mma_sync(acc1, Ah, Bl, acc1);
            wmma::mma_sync(acc1, Al, Bh, acc1);
        }
        __syncthreads();
        if (c + 2 < NCH) issue(c + 2, buf);
        CP_COMMIT();
    }

    #pragma unroll
    for (int i = 0; i < acc0.num_elements; i++) acc0.x[i] += acc1.x[i];
    wmma::store_matrix_sync(&cs[wm * 16][wn * 16], acc0, 32, wmma::mem_row_major);
    __syncthreads();

    const float* bias = g_bias[layer];
    float* cst = g_c[layer];
    bf16 *oh = g_h_h[nxt][layer], *ol = g_h_l[nxt][layer];
    int j0 = n0 >> 2;   // 8 hidden units per block
    for (int p = tid; p < BAT * 8; p += 256) {
        int b = p >> 3;
        int u = p & 7;
        float gi = cs[b][4 * u + 0] + bias[n0 + 4 * u + 0];
        float gf = cs[b][4 * u + 1] + bias[n0 + 4 * u + 1];
        float gg = cs[b][4 * u + 2] + bias[n0 + 4 * u + 2];
        float go = cs[b][4 * u + 3] + bias[n0 + 4 * u + 3];
        gi = 1.0f / (1.0f + expf(-gi));
        gf = 1.0f / (1.0f + expf(-gf));
        gg = tanhf(gg);
        go = 1.0f / (1.0f + expf(-go));
        int j = j0 + u;
        float cv = gf * cst[b * HID + j] + gi * gg;
        cst[b * HID + j] = cv;
        float hv = go * tanhf(cv);
        split2(hv, oh[b * HID + j], ol[b * HID + j]);
    }
}

// ---------------- decoder: out = h2 @ dec_w^T + dec_b ----------------
// grid = 6 blocks of 32 out-cols, same pipeline, K = 1024 (16 chunks)
__global__ __launch_bounds__(256) void dec_step(int t, float* __restrict__ out) {
    extern __shared__ char sraw[];
    bf16* sA_h = (bf16*)sraw;
    bf16* sA_l = sA_h + 2 * 64 * SMSA;
    bf16* sB_h = sA_l + 2 * 64 * SMSA;
    bf16* sB_l = sB_h + 2 * 32 * SMSA;
    float (*cs)[32] = (float (*)[32])(sB_l + 2 * 32 * SMSA);

    int nxt = (t & 1) ^ 1;
    const bf16* ah = g_h_h[nxt][2];
    const bf16* al = g_h_l[nxt][2];
    int n0  = blockIdx.x * 32;
    int tid = threadIdx.x;

    auto issue = [&](int c, int buf) {
        int k0 = c * 64;
        bf16* dAh = sA_h + buf * 64 * SMSA;
        bf16* dAl = sA_l + buf * 64 * SMSA;
        #pragma unroll
        for (int i = tid; i < 512; i += 256) {
            int r = i >> 3, s = (i & 7) * 8;
            cp16(dAh + r * SMSA + s, ah + r * HID + k0 + s);
            cp16(dAl + r * SMSA + s, al + r * HID + k0 + s);
        }
        {
            int r = tid >> 3, s = (tid & 7) * 8;
            bf16* dBh = sB_h + buf * 32 * SMSA;
            bf16* dBl = sB_l + buf * 32 * SMSA;
            int boff = (n0 + r) * HID + k0 + s;
            cp16(dBh + r * SMSA + s, g_dec_h + boff);
            cp16(dBl + r * SMSA + s, g_dec_l + boff);
        }
    };

    int warp = tid >> 5;
    int wm = warp & 3;
    int wn = warp >> 2;

    wmma::fragment<wmma::accumulator, 16, 16, 16, float> acc0, acc1;
    wmma::fill_fragment(acc0, 0.0f);
    wmma::fill_fragment(acc1, 0.0f);
    wmma::fragment<wmma::matrix_a, 16, 16, 16, bf16, wmma::row_major> Ah, Al;
    wmma::fragment<wmma::matrix_b, 16, 16, 16, bf16, wmma::col_major> Bh, Bl;

    issue(0, 0); CP_COMMIT();
    issue(1, 1); CP_COMMIT();

    const int NCH = HID / 64;
    for (int c = 0; c < NCH; c++) {
        CP_WAIT1();
        __syncthreads();
        int buf = c & 1;
        const bf16* pAh = sA_h + buf * 64 * SMSA + wm * 16 * SMSA;
        const bf16* pAl = sA_l + buf * 64 * SMSA + wm * 16 * SMSA;
        const bf16* pBh = sB_h + buf * 32 * SMSA + wn * 16 * SMSA;
        const bf16* pBl = sB_l + buf * 32 * SMSA + wn * 16 * SMSA;
        #pragma unroll
        for (int kk = 0; kk < 4; kk++) {
            wmma::load_matrix_sync(Ah, pAh + kk * 16, SMSA);
            wmma::load_matrix_sync(Al, pAl + kk * 16, SMSA);
            wmma::load_matrix_sync(Bh, pBh + kk * 16, SMSA);
            wmma::load_matrix_sync(Bl, pBl + kk * 16, SMSA);
            wmma::mma_sync(acc0, Ah, Bh, acc0);
            wmma::mma_sync(acc1, Ah, Bl, acc1);
            wmma::mma_sync(acc1, Al, Bh, acc1);
        }
        __syncthreads();
        if (c + 2 < NCH) issue(c + 2, buf);
        CP_COMMIT();
    }

    #pragma unroll
    for (int i = 0; i < acc0.num_elements; i++) acc0.x[i] += acc1.x[i];
    wmma::store_matrix_sync(&cs[wm * 16][wn * 16], acc0, 32, wmma::mem_row_major);
    __syncthreads();

    for (int p = tid; p < BAT * 32; p += 256) {
        int b = p >> 5;
        int u = p & 31;
        int col = n0 + u;
        if (col < INS) {
            float v = cs[b][u] + g_dbias[col];
            out[b * (TT * INS) + t * INS + col] = v;
            split2(v, g_po_h[b * KX0 + col], g_po_l[b * KX0 + col]);
        }
    }
}

// ---------------- launch ----------------
extern "C" void kernel_launch(void* const* d_in, const int* in_sizes, int n_in,
                              void* d_out, int out_size) {
    const float* rs    = (const float*)d_in[0];
    const float* wih1  = (const float*)d_in[1];
    const float* whh1  = (const float*)d_in[2];
    const float* bih1  = (const float*)d_in[3];
    const float* bhh1  = (const float*)d_in[4];
    const float* wih2  = (const float*)d_in[5];
    const float* whh2  = (const float*)d_in[6];
    const float* bih2  = (const float*)d_in[7];
    const float* bhh2  = (const float*)d_in[8];
    const float* wih3  = (const float*)d_in[9];
    const float* whh3  = (const float*)d_in[10];
    const float* bih3  = (const float*)d_in[11];
    const float* bhh3  = (const float*)d_in[12];
    const float* decw  = (const float*)d_in[13];
    const float* decb  = (const float*)d_in[14];
    float* out = (float*)d_out;

    cudaFuncSetAttribute(lstm_step, cudaFuncAttributeMaxDynamicSharedMemorySize, SMEM_BYTES);
    cudaFuncSetAttribute(dec_step,  cudaFuncAttributeMaxDynamicSharedMemorySize, SMEM_BYTES);

    prep_w<<<2048, 256>>>(wih1, whh1, 0, KX0, INS);
    prep_w<<<2048, 256>>>(wih2, whh2, 1, HID, HID);
    prep_w<<<2048, 256>>>(wih3, whh3, 2, HID, HID);
    prep_dec<<<512, 256>>>(decw);
    prep_bias<<<16, 256>>>(bih1, bhh1, 0);
    prep_bias<<<16, 256>>>(bih2, bhh2, 1);
    prep_bias<<<16, 256>>>(bih3, bhh3, 2);
    prep_dbias<<<1, 256>>>(decb);
    prep_frames<<<1024, 256>>>(rs);
    prep_zero<<<512, 256>>>();

    for (int t = 0; t < TT; t++) {
        int use_frame = ((t % 10) < 5) ? 1 : 0;
        lstm_step<<<128, 256, SMEM_BYTES>>>(0, t, use_frame);
        lstm_step<<<128, 256, SMEM_BYTES>>>(1, t, use_frame);
        lstm_step<<<128, 256, SMEM_BYTES>>>(2, t, use_frame);
        dec_step<<<6, 256, SMEM_BYTES>>>(t, out);
    }
}

// round 4
// speedup vs baseline: 3.3689x; 1.0863x over previous
#include <cuda_runtime.h>
#include <cuda_bf16.h>
#include <mma.h>
#include <cstdint>

using namespace nvcuda;
typedef __nv_bfloat16 bf16;

#define HID   1024
#define G4    4096
#define BAT   64
#define TT    100
#define INS   171
#define KX    192
#define NB    128
#define SMSA  72

// ---------------- persistent device buffers ----------------
// slots: 0..2 = Wh layer0..2 (whh1..3), 3 = Wx layer1 (wih2), 4 = Wx layer2 (wih3)
__device__ bf16  g_w_h[5][G4 * HID];
__device__ bf16  g_w_l[5][G4 * HID];
__device__ bf16  g_wx0_h[G4 * KX];
__device__ bf16  g_wx0_l[G4 * KX];
__device__ bf16  g_dec_h[192 * HID];
__device__ bf16  g_dec_l[192 * HID];
__device__ float g_bias[3][G4];
__device__ float g_dbias[192];
__device__ bf16  g_fr_h[TT * BAT * KX];
__device__ bf16  g_fr_l[TT * BAT * KX];
__device__ bf16  g_hst_h[3][BAT * HID];
__device__ bf16  g_hst_l[3][BAT * HID];
__device__ bf16  g_po_h[BAT * KX];
__device__ bf16  g_po_l[BAT * KX];
__device__ float g_dpart[4][BAT][192];
__device__ unsigned g_bar_arrive;   // self-resets to 0 each barrier
__device__ unsigned g_bar_gen;      // monotonically increases (wraps OK)

__device__ __forceinline__ void split2(float v, bf16& hi, bf16& lo) {
    hi = __float2bfloat16(v);
    lo = __float2bfloat16(v - __bfloat162float(hi));
}

__device__ __forceinline__ void cp16(void* dst, const void* src) {
    unsigned int d = (unsigned int)__cvta_generic_to_shared(dst);
    asm volatile("cp.async.cg.shared.global [%0], [%1], 16;" :: "r"(d), "l"(src));
}
#define CP_COMMIT() asm volatile("cp.async.commit_group;")
#define CP_WAIT1()  asm volatile("cp.async.wait_group 1;")

// ---------------- grid-wide barrier (all NB blocks resident) ----------------
__device__ __forceinline__ void gbar() {
    __syncthreads();
    if (threadIdx.x == 0) {
        __threadfence();
        unsigned gen = *(volatile unsigned*)&g_bar_gen;
        if (atomicAdd(&g_bar_arrive, 1u) == NB - 1u) {
            g_bar_arrive = 0;
            __threadfence();
            *(volatile unsigned*)&g_bar_gen = gen + 1u;
        } else {
            while (*(volatile unsigned*)&g_bar_gen == gen) { }
        }
        __threadfence();
    }
    __syncthreads();
}

// ---------------- prep kernels ----------------
__global__ void prep_w1024(const float* __restrict__ src, int slot) {
    bf16* dh = g_w_h[slot];
    bf16* dl = g_w_l[slot];
    int n = G4 * HID;
    for (int i = blockIdx.x * blockDim.x + threadIdx.x; i < n; i += gridDim.x * blockDim.x) {
        int col = i >> 10, k = i & 1023;
        int j = col >> 2, g = col & 3;
        float v = src[(g * HID + j) * HID + k];
        split2(v, dh[i], dl[i]);
    }
}

__global__ void prep_wx0(const float* __restrict__ src) {
    int n = G4 * KX;
    for (int i = blockIdx.x * blockDim.x + threadIdx.x; i < n; i += gridDim.x * blockDim.x) {
        int col = i / KX, k = i - col * KX;
        int j = col >> 2, g = col & 3;
        float v = (k < INS) ? src[(g * HID + j) * INS + k] : 0.0f;
        split2(v, g_wx0_h[i], g_wx0_l[i]);
    }
}

__global__ void prep_dec(const float* __restrict__ src) {
    int n = 192 * HID;
    for (int i = blockIdx.x * blockDim.x + threadIdx.x; i < n; i += gridDim.x * blockDim.x) {
        int r = i >> 10, k = i & 1023;
        float v = (r < INS) ? src[r * HID + k] : 0.0f;
        split2(v, g_dec_h[i], g_dec_l[i]);
    }
}

__global__ void prep_bias(const float* __restrict__ bi, const float* __restrict__ bh, int layer) {
    for (int i = blockIdx.x * blockDim.x + threadIdx.x; i < G4; i += gridDim.x * blockDim.x) {
        int j = i >> 2, g = i & 3;
        g_bias[layer][i] = bi[g * HID + j] + bh[g * HID + j];
    }
}

__global__ void prep_dbias(const float* __restrict__ db) {
    for (int i = blockIdx.x * blockDim.x + threadIdx.x; i < 192; i += gridDim.x * blockDim.x)
        g_dbias[i] = (i < INS) ? db[i] : 0.0f;
}

__global__ void prep_frames(const float* __restrict__ rs) {
    int n = TT * BAT * KX;
    for (int i = blockIdx.x * blockDim.x + threadIdx.x; i < n; i += gridDim.x * blockDim.x) {
        int t   = i / (BAT * KX);
        int rem = i - t * (BAT * KX);
        int b = rem / KX, k = rem - b * KX;
        float v = (k < INS) ? rs[(b * TT + t) * INS + k] : 0.0f;
        split2(v, g_fr_h[i], g_fr_l[i]);
    }
}

// ---------------- pipelined GEMM core (adds into accMain) ----------------
// A [64 x K] (lda), B [cols x K] row-major K-contig (ldb); 32 cols from bcol0.
// nch = K/64 chunks.
template <typename AccFrag>
__device__ __forceinline__ void run_gemm(
    AccFrag& accMain,
    bf16* sA_h, bf16* sA_l, bf16* sB_h, bf16* sB_l,
    int tid, int wm, int wn,
    const bf16* __restrict__ ah, const bf16* __restrict__ al, int lda,
    const bf16* __restrict__ bh, const bf16* __restrict__ bl, int ldb,
    int bcol0, int nch)
{
    auto issue = [&](int c, int buf) {
        int k0 = c * 64;
        bf16* dAh = sA_h + buf * 64 * SMSA;
        bf16* dAl = sA_l + buf * 64 * SMSA;
        #pragma unroll
        for (int i = tid; i < 512; i += 256) {
            int r = i >> 3, s = (i & 7) * 8;
            cp16(dAh + r * SMSA + s, ah + r * lda + k0 + s);
            cp16(dAl + r * SMSA + s, al + r * lda + k0 + s);
        }
        {
            int r = tid >> 3, s = (tid & 7) * 8;
            bf16* dBh = sB_h + buf * 32 * SMSA;
            bf16* dBl = sB_l + buf * 32 * SMSA;
            long boff = (long)(bcol0 + r) * ldb + k0 + s;
            cp16(dBh + r * SMSA + s, bh + boff);
            cp16(dBl + r * SMSA + s, bl + boff);
        }
    };

    wmma::fragment<wmma::accumulator, 16, 16, 16, float> acc1;
    wmma::fill_fragment(acc1, 0.0f);
    wmma::fragment<wmma::matrix_a, 16, 16, 16, bf16, wmma::row_major> Ah, Al;
    wmma::fragment<wmma::matrix_b, 16, 16, 16, bf16, wmma::col_major> Bh, Bl;

    issue(0, 0); CP_COMMIT();
    issue(1, 1); CP_COMMIT();

    for (int c = 0; c < nch; c++) {
        CP_WAIT1();
        __syncthreads();
        int buf = c & 1;
        const bf16* pAh = sA_h + buf * 64 * SMSA + wm * 16 * SMSA;
        const bf16* pAl = sA_l + buf * 64 * SMSA + wm * 16 * SMSA;
        const bf16* pBh = sB_h + buf * 32 * SMSA + wn * 16 * SMSA;
        const bf16* pBl = sB_l + buf * 32 * SMSA + wn * 16 * SMSA;
        #pragma unroll
        for (int kk = 0; kk < 4; kk++) {
            wmma::load_matrix_sync(Ah, pAh + kk * 16, SMSA);
            wmma::load_matrix_sync(Al, pAl + kk * 16, SMSA);
            wmma::load_matrix_sync(Bh, pBh + kk * 16, SMSA);
            wmma::load_matrix_sync(Bl, pBl + kk * 16, SMSA);
            wmma::mma_sync(accMain, Ah, Bh, accMain);
            wmma::mma_sync(acc1, Ah, Bl, acc1);
            wmma::mma_sync(acc1, Al, Bh, acc1);
        }
        __syncthreads();
        if (c + 2 < nch) issue(c + 2, buf);
        CP_COMMIT();
    }
    #pragma unroll
    for (int i = 0; i < accMain.num_elements; i++) accMain.x[i] += acc1.x[i];
}

// ---------------- persistent kernel: entire T loop ----------------
#define SMEM_PIPE  ((2*64*SMSA + 2*32*SMSA) * 2 * 2)   // 55296 B
#define SMEM_BYTES (SMEM_PIPE + 64*32*4 + 3*64*8*4)    // + cs + c_state = 69632 B

__global__ __launch_bounds__(256) void acLSTM_persist(float* __restrict__ out) {
    extern __shared__ char sraw[];
    bf16* sA_h = (bf16*)sraw;
    bf16* sA_l = sA_h + 2 * 64 * SMSA;
    bf16* sB_h = sA_l + 2 * 64 * SMSA;
    bf16* sB_l = sB_h + 2 * 32 * SMSA;
    float (*cs)[32] = (float (*)[32])(sB_l + 2 * 32 * SMSA);
    float* c_state = (float*)(cs + 64);   // [3][64][8]

    const int tid  = threadIdx.x;
    const int blk  = blockIdx.x;
    const int warp = tid >> 5;
    const int wm   = warp & 3;
    const int wn   = warp >> 2;
    const int n0   = blk * 32;

    for (int i = tid; i < 3 * 64 * 8; i += 256) c_state[i] = 0.0f;
    __syncthreads();

    wmma::fragment<wmma::accumulator, 16, 16, 16, float> acc[3], accD;

    auto cell = [&](int layer, wmma::fragment<wmma::accumulator, 16, 16, 16, float>& a) {
        wmma::store_matrix_sync(&cs[wm * 16][wn * 16], a, 32, wmma::mem_row_major);
        __syncthreads();
        const float* bias = g_bias[layer];
        float* cst = c_state + layer * 64 * 8;
        bf16* oh = g_hst_h[layer];
        bf16* ol = g_hst_l[layer];
        for (int p = tid; p < 64 * 8; p += 256) {
            int b = p >> 3, u = p & 7;
            float gi = cs[b][4 * u + 0] + bias[n0 + 4 * u + 0];
            float gf = cs[b][4 * u + 1] + bias[n0 + 4 * u + 1];
            float gg = cs[b][4 * u + 2] + bias[n0 + 4 * u + 2];
            float go = cs[b][4 * u + 3] + bias[n0 + 4 * u + 3];
            gi = 1.0f / (1.0f + expf(-gi));
            gf = 1.0f / (1.0f + expf(-gf));
            gg = tanhf(gg);
            go = 1.0f / (1.0f + expf(-go));
            float cv = gf * cst[b * 8 + u] + gi * gg;
            cst[b * 8 + u] = cv;
            float hv = go * tanhf(cv);
            int j = (n0 >> 2) + u;
            split2(hv, oh[b * HID + j], ol[b * HID + j]);
        }
        __syncthreads();
    };

    auto dec_partial = [&]() {   // blocks 0..23
        int d = blk >> 2, ks = blk & 3;
        wmma::fill_fragment(accD, 0.0f);
        run_gemm(accD, sA_h, sA_l, sB_h, sB_l, tid, wm, wn,
                 g_hst_h[2] + ks * 256, g_hst_l[2] + ks * 256, HID,
                 g_dec_h + ks * 256,    g_dec_l + ks * 256,    HID,
                 d * 32, 4);
        wmma::store_matrix_sync(&g_dpart[ks][wm * 16][d * 32 + wn * 16], accD, 192,
                                wmma::mem_row_major);
    };

    auto dec_finalize = [&](int tprev) {   // blocks 0..5
        for (int p = tid; p < 64 * 32; p += 256) {
            int b = p >> 5, u = p & 31;
            int col = blk * 32 + u;
            float v = g_dpart[0][b][col] + g_dpart[1][b][col] +
                      g_dpart[2][b][col] + g_dpart[3][b][col] + g_dbias[col];
            if (col < INS) {
                out[b * (TT * INS) + tprev * INS + col] = v;
                split2(v, g_po_h[b * KX + col], g_po_l[b * KX + col]);
            } else {
                g_po_h[b * KX + col] = __float2bfloat16(0.0f);
                g_po_l[b * KX + col] = __float2bfloat16(0.0f);
            }
        }
    };

    for (int t = 0; t < TT; t++) {
        bool cond = (t % 10) < 5;

        // ---- Ph1: recurrent GEMMs (all 3 layers) + frame x-GEMM + dec(t-1) partials
        wmma::fill_fragment(acc[0], 0.0f);
        wmma::fill_fragment(acc[1], 0.0f);
        wmma::fill_fragment(acc[2], 0.0f);
        if (t > 0) {
            run_gemm(acc[0], sA_h, sA_l, sB_h, sB_l, tid, wm, wn,
                     g_hst_h[0], g_hst_l[0], HID, g_w_h[0], g_w_l[0], HID, n0, 16);
            run_gemm(acc[1], sA_h, sA_l, sB_h, sB_l, tid, wm, wn,
                     g_hst_h[1], g_hst_l[1], HID, g_w_h[1], g_w_l[1], HID, n0, 16);
            run_gemm(acc[2], sA_h, sA_l, sB_h, sB_l, tid, wm, wn,
                     g_hst_h[2], g_hst_l[2], HID, g_w_h[2], g_w_l[2], HID, n0, 16);
        }
        if (cond) {
            run_gemm(acc[0], sA_h, sA_l, sB_h, sB_l, tid, wm, wn,
                     g_fr_h + t * BAT * KX, g_fr_l + t * BAT * KX, KX,
                     g_wx0_h, g_wx0_l, KX, n0, 3);
        }
        if (t > 0 && blk < 24) dec_partial();
        gbar();

        // ---- Ph2: dec finalize -> out[t-1], po ; then cell0 (with po GEMM if cond==0)
        if (t > 0 && blk < 6) dec_finalize(t - 1);
        if (!cond) {
            gbar();
            run_gemm(acc[0], sA_h, sA_l, sB_h, sB_l, tid, wm, wn,
                     g_po_h, g_po_l, KX, g_wx0_h, g_wx0_l, KX, n0, 3);
        }
        cell(0, acc[0]);
        gbar();

        // ---- Ph3: h0 -> layer1
        run_gemm(acc[1], sA_h, sA_l, sB_h, sB_l, tid, wm, wn,
                 g_hst_h[0], g_hst_l[0], HID, g_w_h[3], g_w_l[3], HID, n0, 16);
        cell(1, acc[1]);
        gbar();

        // ---- Ph4: h1 -> layer2
        run_gemm(acc[2], sA_h, sA_l, sB_h, sB_l, tid, wm, wn,
                 g_hst_h[1], g_hst_l[1], HID, g_w_h[4], g_w_l[4], HID, n0, 16);
        cell(2, acc[2]);
        gbar();
    }

    // ---- final decoder for t = 99
    if (blk < 24) dec_partial();
    gbar();
    if (blk < 6) dec_finalize(TT - 1);
}

// ---------------- launch ----------------
extern "C" void kernel_launch(void* const* d_in, const int* in_sizes, int n_in,
                              void* d_out, int out_size) {
    const float* rs    = (const float*)d_in[0];
    const float* wih1  = (const float*)d_in[1];
    const float* whh1  = (const float*)d_in[2];
    const float* bih1  = (const float*)d_in[3];
    const float* bhh1  = (const float*)d_in[4];
    const float* wih2  = (const float*)d_in[5];
    const float* whh2  = (const float*)d_in[6];
    const float* bih2  = (const float*)d_in[7];
    const float* bhh2  = (const float*)d_in[8];
    const float* wih3  = (const float*)d_in[9];
    const float* whh3  = (const float*)d_in[10];
    const float* bih3  = (const float*)d_in[11];
    const float* bhh3  = (const float*)d_in[12];
    const float* decw  = (const float*)d_in[13];
    const float* decb  = (const float*)d_in[14];
    float* out = (float*)d_out;

    cudaFuncSetAttribute(acLSTM_persist, cudaFuncAttributeMaxDynamicSharedMemorySize, SMEM_BYTES);

    prep_w1024<<<2048, 256>>>(whh1, 0);
    prep_w1024<<<2048, 256>>>(whh2, 1);
    prep_w1024<<<2048, 256>>>(whh3, 2);
    prep_w1024<<<2048, 256>>>(wih2, 3);
    prep_w1024<<<2048, 256>>>(wih3, 4);
    prep_wx0<<<512, 256>>>(wih1);
    prep_dec<<<512, 256>>>(decw);
    prep_bias<<<16, 256>>>(bih1, bhh1, 0);
    prep_bias<<<16, 256>>>(bih2, bhh2, 1);
    prep_bias<<<16, 256>>>(bih3, bhh3, 2);
    prep_dbias<<<1, 256>>>(decb);
    prep_frames<<<1024, 256>>>(rs);

    acLSTM_persist<<<NB, 256, SMEM_BYTES>>>(out);
}

// round 5
// speedup vs baseline: 3.3845x; 1.0046x over previous
#include <cuda_runtime.h>
#include <cuda_bf16.h>
#include <mma.h>
#include <cstdint>

using namespace nvcuda;
typedef __nv_bfloat16 bf16;

#define HID   1024
#define G4    4096
#define BAT   64
#define TT    100
#define INS   171
#define KX    192
#define NB    128
#define SMSA  72

// ---------------- persistent device buffers ----------------
// slots: 0..2 = Wh layer0..2 (whh1..3), 3 = Wx layer1 (wih2), 4 = Wx layer2 (wih3)
__device__ bf16  g_w_h[5][G4 * HID];
__device__ bf16  g_w_l[5][G4 * HID];
__device__ bf16  g_wx0_h[G4 * KX];
__device__ bf16  g_wx0_l[G4 * KX];
__device__ bf16  g_dec_h[192 * HID];
__device__ bf16  g_dec_l[192 * HID];
__device__ float g_bias[3][G4];
__device__ float g_dbias[192];
__device__ bf16  g_fr_h[TT * BAT * KX];
__device__ bf16  g_fr_l[TT * BAT * KX];
__device__ bf16  g_hst_h[3][BAT * HID];
__device__ bf16  g_hst_l[3][BAT * HID];
__device__ bf16  g_po_h[BAT * KX];
__device__ bf16  g_po_l[BAT * KX];
__device__ float g_dpart[4][BAT][192];
__device__ unsigned g_bar_arrive;   // self-resets to 0 each barrier
__device__ unsigned g_bar_gen;      // monotonically increases (wraps OK)

__device__ __forceinline__ void split2(float v, bf16& hi, bf16& lo) {
    hi = __float2bfloat16(v);
    lo = __float2bfloat16(v - __bfloat162float(hi));
}

__device__ __forceinline__ void cp16(void* dst, const void* src) {
    unsigned int d = (unsigned int)__cvta_generic_to_shared(dst);
    asm volatile("cp.async.cg.shared.global [%0], [%1], 16;" :: "r"(d), "l"(src));
}
#define CP_COMMIT() asm volatile("cp.async.commit_group;")
#define CP_WAIT1()  asm volatile("cp.async.wait_group 1;")

// ---------------- grid-wide barrier (all NB blocks resident) ----------------
__device__ __forceinline__ void gbar() {
    __syncthreads();
    if (threadIdx.x == 0) {
        __threadfence();
        unsigned gen = *(volatile unsigned*)&g_bar_gen;
        if (atomicAdd(&g_bar_arrive, 1u) == NB - 1u) {
            g_bar_arrive = 0;
            __threadfence();
            *(volatile unsigned*)&g_bar_gen = gen + 1u;
        } else {
            while (*(volatile unsigned*)&g_bar_gen == gen) { }
        }
        __threadfence();
    }
    __syncthreads();
}

// ---------------- prep kernels ----------------
__global__ void prep_w1024(const float* __restrict__ src, int slot) {
    bf16* dh = g_w_h[slot];
    bf16* dl = g_w_l[slot];
    int n = G4 * HID;
    for (int i = blockIdx.x * blockDim.x + threadIdx.x; i < n; i += gridDim.x * blockDim.x) {
        int col = i >> 10, k = i & 1023;
        int j = col >> 2, g = col & 3;
        float v = src[(g * HID + j) * HID + k];
        split2(v, dh[i], dl[i]);
    }
}

__global__ void prep_wx0(const float* __restrict__ src) {
    int n = G4 * KX;
    for (int i = blockIdx.x * blockDim.x + threadIdx.x; i < n; i += gridDim.x * blockDim.x) {
        int col = i / KX, k = i - col * KX;
        int j = col >> 2, g = col & 3;
        float v = (k < INS) ? src[(g * HID + j) * INS + k] : 0.0f;
        split2(v, g_wx0_h[i], g_wx0_l[i]);
    }
}

__global__ void prep_dec(const float* __restrict__ src) {
    int n = 192 * HID;
    for (int i = blockIdx.x * blockDim.x + threadIdx.x; i < n; i += gridDim.x * blockDim.x) {
        int r = i >> 10, k = i & 1023;
        float v = (r < INS) ? src[r * HID + k] : 0.0f;
        split2(v, g_dec_h[i], g_dec_l[i]);
    }
}

__global__ void prep_bias(const float* __restrict__ bi, const float* __restrict__ bh, int layer) {
    for (int i = blockIdx.x * blockDim.x + threadIdx.x; i < G4; i += gridDim.x * blockDim.x) {
        int j = i >> 2, g = i & 3;
        g_bias[layer][i] = bi[g * HID + j] + bh[g * HID + j];
    }
}

__global__ void prep_dbias(const float* __restrict__ db) {
    for (int i = blockIdx.x * blockDim.x + threadIdx.x; i < 192; i += gridDim.x * blockDim.x)
        g_dbias[i] = (i < INS) ? db[i] : 0.0f;
}

__global__ void prep_frames(const float* __restrict__ rs) {
    int n = TT * BAT * KX;
    for (int i = blockIdx.x * blockDim.x + threadIdx.x; i < n; i += gridDim.x * blockDim.x) {
        int t   = i / (BAT * KX);
        int rem = i - t * (BAT * KX);
        int b = rem / KX, k = rem - b * KX;
        float v = (k < INS) ? rs[(b * TT + t) * INS + k] : 0.0f;
        split2(v, g_fr_h[i], g_fr_l[i]);
    }
}

// ---------------- pipelined GEMM core (adds into accMain) ----------------
// A [64 x K] (lda), B [cols x K] row-major K-contig (ldb); 32 cols from bcol0.
// nch = K/64 chunks.
template <typename AccFrag>
__device__ __forceinline__ void run_gemm(
    AccFrag& accMain,
    bf16* sA_h, bf16* sA_l, bf16* sB_h, bf16* sB_l,
    int tid, int wm, int wn,
    const bf16* __restrict__ ah, const bf16* __restrict__ al, int lda,
    const bf16* __restrict__ bh, const bf16* __restrict__ bl, int ldb,
    int bcol0, int nch)
{
    auto issue = [&](int c, int buf) {
        int k0 = c * 64;
        bf16* dAh = sA_h + buf * 64 * SMSA;
        bf16* dAl = sA_l + buf * 64 * SMSA;
        #pragma unroll
        for (int i = tid; i < 512; i += 256) {
            int r = i >> 3, s = (i & 7) * 8;
            cp16(dAh + r * SMSA + s, ah + r * lda + k0 + s);
            cp16(dAl + r * SMSA + s, al + r * lda + k0 + s);
        }
        {
            int r = tid >> 3, s = (tid & 7) * 8;
            bf16* dBh = sB_h + buf * 32 * SMSA;
            bf16* dBl = sB_l + buf * 32 * SMSA;
            long boff = (long)(bcol0 + r) * ldb + k0 + s;
            cp16(dBh + r * SMSA + s, bh + boff);
            cp16(dBl + r * SMSA + s, bl + boff);
        }
    };

    wmma::fragment<wmma::accumulator, 16, 16, 16, float> acc1;
    wmma::fill_fragment(acc1, 0.0f);
    wmma::fragment<wmma::matrix_a, 16, 16, 16, bf16, wmma::row_major> Ah, Al;
    wmma::fragment<wmma::matrix_b, 16, 16, 16, bf16, wmma::col_major> Bh, Bl;

    issue(0, 0); CP_COMMIT();
    issue(1, 1); CP_COMMIT();

    for (int c = 0; c < nch; c++) {
        CP_WAIT1();
        __syncthreads();
        int buf = c & 1;
        const bf16* pAh = sA_h + buf * 64 * SMSA + wm * 16 * SMSA;
        const bf16* pAl = sA_l + buf * 64 * SMSA + wm * 16 * SMSA;
        const bf16* pBh = sB_h + buf * 32 * SMSA + wn * 16 * SMSA;
        const bf16* pBl = sB_l + buf * 32 * SMSA + wn * 16 * SMSA;
        #pragma unroll
        for (int kk = 0; kk < 4; kk++) {
            wmma::load_matrix_sync(Ah, pAh + kk * 16, SMSA);
            wmma::load_matrix_sync(Al, pAl + kk * 16, SMSA);
            wmma::load_matrix_sync(Bh, pBh + kk * 16, SMSA);
            wmma::load_matrix_sync(Bl, pBl + kk * 16, SMSA);
            wmma::mma_sync(accMain, Ah, Bh, accMain);
            wmma::mma_sync(acc1, Ah, Bl, acc1);
            wmma::mma_sync(acc1, Al, Bh, acc1);
        }
        __syncthreads();
        if (c + 2 < nch) issue(c + 2, buf);
        CP_COMMIT();
    }
    #pragma unroll
    for (int i = 0; i < accMain.num_elements; i++) accMain.x[i] += acc1.x[i];
}

// ---------------- persistent kernel: entire T loop ----------------
#define SMEM_PIPE  ((2*64*SMSA + 2*32*SMSA) * 2 * 2)   // 55296 B
#define SMEM_BYTES (SMEM_PIPE + 64*32*4 + 3*64*8*4)    // + cs + c_state = 69632 B

__global__ __launch_bounds__(256) void acLSTM_persist(float* __restrict__ out) {
    extern __shared__ char sraw[];
    bf16* sA_h = (bf16*)sraw;
    bf16* sA_l = sA_h + 2 * 64 * SMSA;
    bf16* sB_h = sA_l + 2 * 64 * SMSA;
    bf16* sB_l = sB_h + 2 * 32 * SMSA;
    float (*cs)[32] = (float (*)[32])(sB_l + 2 * 32 * SMSA);
    float* c_state = (float*)(cs + 64);   // [3][64][8]

    const int tid  = threadIdx.x;
    const int blk  = blockIdx.x;
    const int warp = tid >> 5;
    const int wm   = warp & 3;
    const int wn   = warp >> 2;
    const int n0   = blk * 32;

    for (int i = tid; i < 3 * 64 * 8; i += 256) c_state[i] = 0.0f;
    __syncthreads();

    wmma::fragment<wmma::accumulator, 16, 16, 16, float> acc[3], accD;

    auto cell = [&](int layer, wmma::fragment<wmma::accumulator, 16, 16, 16, float>& a) {
        wmma::store_matrix_sync(&cs[wm * 16][wn * 16], a, 32, wmma::mem_row_major);
        __syncthreads();
        const float* bias = g_bias[layer];
        float* cst = c_state + layer * 64 * 8;
        bf16* oh = g_hst_h[layer];
        bf16* ol = g_hst_l[layer];
        for (int p = tid; p < 64 * 8; p += 256) {
            int b = p >> 3, u = p & 7;
            float gi = cs[b][4 * u + 0] + bias[n0 + 4 * u + 0];
            float gf = cs[b][4 * u + 1] + bias[n0 + 4 * u + 1];
            float gg = cs[b][4 * u + 2] + bias[n0 + 4 * u + 2];
            float go = cs[b][4 * u + 3] + bias[n0 + 4 * u + 3];
            gi = 1.0f / (1.0f + expf(-gi));
            gf = 1.0f / (1.0f + expf(-gf));
            gg = tanhf(gg);
            go = 1.0f / (1.0f + expf(-go));
            float cv = gf * cst[b * 8 + u] + gi * gg;
            cst[b * 8 + u] = cv;
            float hv = go * tanhf(cv);
            int j = (n0 >> 2) + u;
            split2(hv, oh[b * HID + j], ol[b * HID + j]);
        }
        __syncthreads();
    };

    auto dec_partial = [&]() {   // blocks 0..23
        int d = blk >> 2, ks = blk & 3;
        wmma::fill_fragment(accD, 0.0f);
        run_gemm(accD, sA_h, sA_l, sB_h, sB_l, tid, wm, wn,
                 g_hst_h[2] + ks * 256, g_hst_l[2] + ks * 256, HID,
                 g_dec_h + ks * 256,    g_dec_l + ks * 256,    HID,
                 d * 32, 4);
        wmma::store_matrix_sync(&g_dpart[ks][wm * 16][d * 32 + wn * 16], accD, 192,
                                wmma::mem_row_major);
    };

    auto dec_finalize = [&](int tprev) {   // blocks 0..5
        for (int p = tid; p < 64 * 32; p += 256) {
            int b = p >> 5, u = p & 31;
            int col = blk * 32 + u;
            float v = g_dpart[0][b][col] + g_dpart[1][b][col] +
                      g_dpart[2][b][col] + g_dpart[3][b][col] + g_dbias[col];
            if (col < INS) {
                out[b * (TT * INS) + tprev * INS + col] = v;
                split2(v, g_po_h[b * KX + col], g_po_l[b * KX + col]);
            } else {
                g_po_h[b * KX + col] = __float2bfloat16(0.0f);
                g_po_l[b * KX + col] = __float2bfloat16(0.0f);
            }
        }
    };

    for (int t = 0; t < TT; t++) {
        bool cond = (t % 10) < 5;

        // ---- Ph1: recurrent GEMMs (all 3 layers) + frame x-GEMM + dec(t-1) partials
        wmma::fill_fragment(acc[0], 0.0f);
        wmma::fill_fragment(acc[1], 0.0f);
        wmma::fill_fragment(acc[2], 0.0f);
        if (t > 0) {
            run_gemm(acc[0], sA_h, sA_l, sB_h, sB_l, tid, wm, wn,
                     g_hst_h[0], g_hst_l[0], HID, g_w_h[0], g_w_l[0], HID, n0, 16);
            run_gemm(acc[1], sA_h, sA_l, sB_h, sB_l, tid, wm, wn,
                     g_hst_h[1], g_hst_l[1], HID, g_w_h[1], g_w_l[1], HID, n0, 16);
            run_gemm(acc[2], sA_h, sA_l, sB_h, sB_l, tid, wm, wn,
                     g_hst_h[2], g_hst_l[2], HID, g_w_h[2], g_w_l[2], HID, n0, 16);
        }
        if (cond) {
            run_gemm(acc[0], sA_h, sA_l, sB_h, sB_l, tid, wm, wn,
                     g_fr_h + t * BAT * KX, g_fr_l + t * BAT * KX, KX,
                     g_wx0_h, g_wx0_l, KX, n0, 3);
        }
        if (t > 0 && blk < 24) dec_partial();
        gbar();

        // ---- Ph2: dec finalize -> out[t-1], po ; then cell0 (with po GEMM if cond==0)
        if (t > 0 && blk < 6) dec_finalize(t - 1);
        if (!cond) {
            gbar();
            run_gemm(acc[0], sA_h, sA_l, sB_h, sB_l, tid, wm, wn,
                     g_po_h, g_po_l, KX, g_wx0_h, g_wx0_l, KX, n0, 3);
        }
        cell(0, acc[0]);
        gbar();

        // ---- Ph3: h0 -> layer1
        run_gemm(acc[1], sA_h, sA_l, sB_h, sB_l, tid, wm, wn,
                 g_hst_h[0], g_hst_l[0], HID, g_w_h[3], g_w_l[3], HID, n0, 16);
        cell(1, acc[1]);
        gbar();

        // ---- Ph4: h1 -> layer2
        run_gemm(acc[2], sA_h, sA_l, sB_h, sB_l, tid, wm, wn,
                 g_hst_h[1], g_hst_l[1], HID, g_w_h[4], g_w_l[4], HID, n0, 16);
        cell(2, acc[2]);
        gbar();
    }

    // ---- final decoder for t = 99
    if (blk < 24) dec_partial();
    gbar();
    if (blk < 6) dec_finalize(TT - 1);
}

// ---------------- launch ----------------
extern "C" void kernel_launch(void* const* d_in, const int* in_sizes, int n_in,
                              void* d_out, int out_size) {
    const float* rs    = (const float*)d_in[0];
    const float* wih1  = (const float*)d_in[1];
    const float* whh1  = (const float*)d_in[2];
    const float* bih1  = (const float*)d_in[3];
    const float* bhh1  = (const float*)d_in[4];
    const float* wih2  = (const float*)d_in[5];
    const float* whh2  = (const float*)d_in[6];
    const float* bih2  = (const float*)d_in[7];
    const float* bhh2  = (const float*)d_in[8];
    const float* wih3  = (const float*)d_in[9];
    const float* whh3  = (const float*)d_in[10];
    const float* bih3  = (const float*)d_in[11];
    const float* bhh3  = (const float*)d_in[12];
    const float* decw  = (const float*)d_in[13];
    const float* decb  = (const float*)d_in[14];
    float* out = (float*)d_out;

    cudaFuncSetAttribute(acLSTM_persist, cudaFuncAttributeMaxDynamicSharedMemorySize, SMEM_BYTES);

    prep_w1024<<<2048, 256>>>(whh1, 0);
    prep_w1024<<<2048, 256>>>(whh2, 1);
    prep_w1024<<<2048, 256>>>(whh3, 2);
    prep_w1024<<<2048, 256>>>(wih2, 3);
    prep_w1024<<<2048, 256>>>(wih3, 4);
    prep_wx0<<<512, 256>>>(wih1);
    prep_dec<<<512, 256>>>(decw);
    prep_bias<<<16, 256>>>(bih1, bhh1, 0);
    prep_bias<<<16, 256>>>(bih2, bhh2, 1);
    prep_bias<<<16, 256>>>(bih3, bhh3, 2);
    prep_dbias<<<1, 256>>>(decb);
    prep_frames<<<1024, 256>>>(rs);

    acLSTM_persist<<<NB, 256, SMEM_BYTES>>>(out);
}

// round 8
// speedup vs baseline: 3.5930x; 1.0616x over previous
#include <cuda_runtime.h>
#include <cuda_fp16.h>
#include <mma.h>
#include <cstdint>

using namespace nvcuda;
typedef __half h16;

#define HID  1024
#define G4   4096
#define BAT  64
#define TT   100
#define INS  171
#define KX   192
#define NB   128
#define SMSA 72
#define NCOND 50

// ---------------- persistent device buffers ----------------
// weight slots: 0..2 = Whh layer0..2, 3 = Wx layer1 (wih2), 4 = Wx layer2 (wih3)
__device__ h16   g_w[5][G4 * HID];
__device__ h16   g_wx0[G4 * KX];
__device__ h16   g_dec[192 * HID];
__device__ float g_bias[3][G4];
__device__ float g_dbias[192];
__device__ h16   g_fr_h[TT * BAT * KX];
__device__ h16   g_fr_l[TT * BAT * KX];
__device__ h16   g_hst_h[3][BAT * HID];
__device__ h16   g_hst_l[3][BAT * HID];
__device__ h16   g_po_h[BAT * KX];
__device__ h16   g_po_l[BAT * KX];
__device__ float g_gate[3][BAT * G4];        // recurrent-gate partials
__device__ float g_gx[NCOND][BAT * G4];      // precomputed frame-gate partials
__device__ unsigned g_arr[NB];
__device__ unsigned g_rel;

__device__ __forceinline__ void split2h(float v, h16& hi, h16& lo) {
    hi = __float2half(v);
    lo = __float2half(v - __half2float(hi));
}
__device__ __forceinline__ void cp16(void* dst, const void* src) {
    unsigned d = (unsigned)__cvta_generic_to_shared(dst);
    asm volatile("cp.async.cg.shared.global [%0], [%1], 16;" :: "r"(d), "l"(src));
}
#define CP_COMMIT() asm volatile("cp.async.commit_group;")
#define CP_WAITG1() asm volatile("cp.async.wait_group 1;")

// ---------------- cheap grid barrier (flag array + parallel poll) ----------------
__device__ __forceinline__ void gbar(unsigned gen) {
    __syncthreads();
    if (threadIdx.x == 0) {
        __threadfence();
        *(volatile unsigned*)&g_arr[blockIdx.x] = gen;
    }
    if (blockIdx.x == 0) {
        if (threadIdx.x < NB) {
            while (*(volatile unsigned*)&g_arr[threadIdx.x] < gen) { }
        }
        __syncthreads();
        if (threadIdx.x == 0) {
            __threadfence();
            *(volatile unsigned*)&g_rel = gen;
        }
    } else if (threadIdx.x == 0) {
        while (*(volatile unsigned*)&g_rel < gen) { }
        __threadfence();
    }
    __syncthreads();
}

// ---------------- prep kernels ----------------
__global__ void prep_wh(const float* __restrict__ src, int slot) {
    h16* d = g_w[slot];
    int n = G4 * HID;
    for (int i = blockIdx.x * blockDim.x + threadIdx.x; i < n; i += gridDim.x * blockDim.x) {
        int col = i >> 10, k = i & 1023;
        int j = col >> 2, g = col & 3;
        d[i] = __float2half(src[(g * HID + j) * HID + k]);
    }
}
__global__ void prep_wx0(const float* __restrict__ src) {
    int n = G4 * KX;
    for (int i = blockIdx.x * blockDim.x + threadIdx.x; i < n; i += gridDim.x * blockDim.x) {
        int col = i / KX, k = i - col * KX;
        int j = col >> 2, g = col & 3;
        float v = (k < INS) ? src[(g * HID + j) * INS + k] : 0.0f;
        g_wx0[i] = __float2half(v);
    }
}
__global__ void prep_dec(const float* __restrict__ src) {
    int n = 192 * HID;
    for (int i = blockIdx.x * blockDim.x + threadIdx.x; i < n; i += gridDim.x * blockDim.x) {
        int r = i >> 10, k = i & 1023;
        float v = (r < INS) ? src[r * HID + k] : 0.0f;
        g_dec[i] = __float2half(v);
    }
}
__global__ void prep_bias(const float* __restrict__ bi, const float* __restrict__ bh, int layer) {
    for (int i = blockIdx.x * blockDim.x + threadIdx.x; i < G4; i += gridDim.x * blockDim.x) {
        int j = i >> 2, g = i & 3;
        g_bias[layer][i] = bi[g * HID + j] + bh[g * HID + j];
    }
}
__global__ void prep_dbias(const float* __restrict__ db) {
    for (int i = blockIdx.x * blockDim.x + threadIdx.x; i < 192; i += gridDim.x * blockDim.x)
        g_dbias[i] = (i < INS) ? db[i] : 0.0f;
}
__global__ void prep_frames(const float* __restrict__ rs) {
    int n = TT * BAT * KX;
    for (int i = blockIdx.x * blockDim.x + threadIdx.x; i < n; i += gridDim.x * blockDim.x) {
        int t   = i / (BAT * KX);
        int rem = i - t * (BAT * KX);
        int b = rem / KX, k = rem - b * KX;
        float v = (k < INS) ? rs[(b * TT + t) * INS + k] : 0.0f;
        split2h(v, g_fr_h[i], g_fr_l[i]);
    }
}
__global__ void prep_zero() {
    int gid = blockIdx.x * blockDim.x + threadIdx.x;
    int stride = gridDim.x * blockDim.x;
    for (int i = gid; i < 3 * BAT * HID; i += stride) {
        ((h16*)g_hst_h)[i] = __float2half(0.0f);
        ((h16*)g_hst_l)[i] = __float2half(0.0f);
    }
    for (int i = gid; i < BAT * KX; i += stride) {
        g_po_h[i] = __float2half(0.0f);
        g_po_l[i] = __float2half(0.0f);
    }
    for (int i = gid; i < 3 * BAT * G4; i += stride)
        ((float*)g_gate)[i] = 0.0f;
    for (int i = gid; i < NB; i += stride) g_arr[i] = 0;
    if (gid == 0) g_rel = 0;
}

// ---------------- pipelined fp16 2-product GEMM core ----------------
// A [64 x K] split hi/lo (lda), W [cols x K] single (ldb). Block tile 64 x (NF*32).
// 8 warps: 4 m-warps x 2 n-warps; warp tile 16 x (NF*16). 3-stage cp.async pipeline,
// one __syncthreads per 64-K chunk.
template <int NF>
__device__ __forceinline__ void run_gemm(
    wmma::fragment<wmma::accumulator, 16, 16, 16, float> (&accH)[NF],
    wmma::fragment<wmma::accumulator, 16, 16, 16, float> (&accL)[NF],
    h16* sAh, h16* sAl, h16* sB,
    int tid, int wm, int wn,
    const h16* __restrict__ ah, const h16* __restrict__ al, int lda,
    const h16* __restrict__ bw, int ldb, int bcol0, int nch)
{
    #pragma unroll
    for (int nf = 0; nf < NF; nf++) {
        wmma::fill_fragment(accH[nf], 0.0f);
        wmma::fill_fragment(accL[nf], 0.0f);
    }

    auto issue = [&](int c, int stg) {
        int k0 = c * 64;
        h16* dAh = sAh + stg * 64 * SMSA;
        h16* dAl = sAl + stg * 64 * SMSA;
        #pragma unroll
        for (int u = 0; u < 2; u++) {
            int i = tid + u * 256;
            int r = i >> 3, s = (i & 7) * 8;
            cp16(dAh + r * SMSA + s, ah + r * lda + k0 + s);
            cp16(dAl + r * SMSA + s, al + r * lda + k0 + s);
        }
        h16* dB = sB + stg * (NF * 32) * SMSA;
        #pragma unroll
        for (int u = 0; u < NF; u++) {
            int i = tid + u * 256;
            int r = i >> 3, s = (i & 7) * 8;
            cp16(dB + r * SMSA + s, bw + (long)(bcol0 + r) * ldb + k0 + s);
        }
    };

    wmma::fragment<wmma::matrix_a, 16, 16, 16, h16, wmma::row_major> Ah, Al;
    wmma::fragment<wmma::matrix_b, 16, 16, 16, h16, wmma::col_major> Bf;

    issue(0, 0); CP_COMMIT();
    issue(1, 1); CP_COMMIT();

    for (int c = 0; c < nch; c++) {
        CP_WAITG1();
        __syncthreads();
        int stg = c % 3;
        if (c + 2 < nch) issue(c + 2, (c + 2) % 3);
        CP_COMMIT();
        const h16* pAh = sAh + stg * 64 * SMSA + wm * 16 * SMSA;
        const h16* pAl = sAl + stg * 64 * SMSA + wm * 16 * SMSA;
        const h16* pB  = sB  + stg * (NF * 32) * SMSA + wn * (NF * 16) * SMSA;
        #pragma unroll
        for (int kk = 0; kk < 4; kk++) {
            wmma::load_matrix_sync(Ah, pAh + kk * 16, SMSA);
            wmma::load_matrix_sync(Al, pAl + kk * 16, SMSA);
            #pragma unroll
            for (int nf = 0; nf < NF; nf++) {
                wmma::load_matrix_sync(Bf, pB + nf * 16 * SMSA + kk * 16, SMSA);
                wmma::mma_sync(accH[nf], Ah, Bf, accH[nf]);
                wmma::mma_sync(accL[nf], Al, Bf, accL[nf]);
            }
        }
    }
}

#define SMEM_BYTES (3*64*SMSA*2*2 + 3*128*SMSA*2 + 64*32*4 + 3*64*8*4)

// ---------------- precompute frame-gate partials for all 50 cond steps ----------------
__global__ __launch_bounds__(256) void prep_gx() {
    extern __shared__ char sraw[];
    h16* sAh = (h16*)sraw;
    h16* sAl = sAh + 3 * 64 * SMSA;
    h16* sB  = sAl + 3 * 64 * SMSA;

    int tid = threadIdx.x, warp = tid >> 5, wm = warp & 3, wn = warp >> 2;
    int ci = blockIdx.y;
    int t  = (ci / 5) * 10 + (ci % 5);
    int n0 = blockIdx.x * 128;

    wmma::fragment<wmma::accumulator, 16, 16, 16, float> aH[4], aL[4];
    run_gemm<4>(aH, aL, sAh, sAl, sB, tid, wm, wn,
                g_fr_h + t * BAT * KX, g_fr_l + t * BAT * KX, KX,
                g_wx0, KX, n0, 3);
    #pragma unroll
    for (int nf = 0; nf < 4; nf++) {
        #pragma unroll
        for (int i = 0; i < aH[nf].num_elements; i++) aH[nf].x[i] += aL[nf].x[i];
        wmma::store_matrix_sync(&g_gx[ci][(wm * 16) * G4 + n0 + wn * 64 + nf * 16],
                                aH[nf], G4, wmma::mem_row_major);
    }
}

// ---------------- persistent kernel: whole T loop ----------------
__global__ __launch_bounds__(256) void persist(float* __restrict__ out) {
    extern __shared__ char sraw[];
    h16* sAh = (h16*)sraw;
    h16* sAl = sAh + 3 * 64 * SMSA;
    h16* sB  = sAl + 3 * 64 * SMSA;
    float (*cs)[32] = (float (*)[32])((char*)(sB + 3 * 128 * SMSA));
    float* c_state = (float*)(cs + 64);   // [3][64][8]

    const int tid  = threadIdx.x;
    const int blk  = blockIdx.x;
    const int warp = tid >> 5;
    const int wm   = warp & 3;
    const int wn   = warp >> 2;
    const int n0c  = blk * 32;

    for (int i = tid; i < 3 * 64 * 8; i += 256) c_state[i] = 0.0f;
    __syncthreads();

    unsigned gen = 0;
    wmma::fragment<wmma::accumulator, 16, 16, 16, float> aH4[4], aL4[4];
    wmma::fragment<wmma::accumulator, 16, 16, 16, float> a1H[1], a1L[1];

    auto cell = [&](int lyr, bool useCs, const float* gx) {
        const float* gate = g_gate[lyr];
        const float* bias = g_bias[lyr];
        float* cst = c_state + lyr * 512;
        h16* oh = g_hst_h[lyr];
        h16* ol = g_hst_l[lyr];
        for (int p = tid; p < 512; p += 256) {
            int b = p >> 3, u = p & 7;
            float q[4];
            #pragma unroll
            for (int m = 0; m < 4; m++) {
                int col = n0c + 4 * u + m;
                float v = gate[b * G4 + col] + bias[col];
                if (useCs) v += cs[b][4 * u + m];
                if (gx)    v += gx[b * G4 + col];
                q[m] = v;
            }
            float gi = 1.0f / (1.0f + expf(-q[0]));
            float gf = 1.0f / (1.0f + expf(-q[1]));
            float gg = tanhf(q[2]);
            float go = 1.0f / (1.0f + expf(-q[3]));
            float cv = gf * cst[p] + gi * gg;
            cst[p] = cv;
            float hv = go * tanhf(cv);
            int j = (n0c >> 2) + u;
            split2h(hv, oh[b * HID + j], ol[b * HID + j]);
        }
        __syncthreads();
    };

    auto dec_run = [&](int tprev) {   // blocks 96..101, self-contained N=32 slice
        run_gemm<1>(a1H, a1L, sAh, sAl, sB, tid, wm, wn,
                    g_hst_h[2], g_hst_l[2], HID, g_dec, HID, (blk - 96) * 32, 16);
        #pragma unroll
        for (int i = 0; i < a1H[0].num_elements; i++) a1H[0].x[i] += a1L[0].x[i];
        wmma::store_matrix_sync(&cs[wm * 16][wn * 16], a1H[0], 32, wmma::mem_row_major);
        __syncthreads();
        int dc0 = (blk - 96) * 32;
        for (int p = tid; p < 2048; p += 256) {
            int b = p >> 5, u = p & 31;
            int col = dc0 + u;
            float v = cs[b][u] + g_dbias[col];
            if (col < INS) {
                out[b * (TT * INS) + tprev * INS + col] = v;
                split2h(v, g_po_h[b * KX + col], g_po_l[b * KX + col]);
            } else {
                g_po_h[b * KX + col] = __float2half(0.0f);
                g_po_l[b * KX + col] = __float2half(0.0f);
            }
        }
    };

    for (int t = 0; t < TT; t++) {
        bool cond = (t % 10) < 5;

        // ---- Ph1: recurrent GEMMs (3 layers concurrently on 96 blocks) + decoder(t-1)
        if (t > 0) {
            if (blk < 96) {
                int lyr = blk >> 5;
                int n0  = (blk & 31) * 128;
                run_gemm<4>(aH4, aL4, sAh, sAl, sB, tid, wm, wn,
                            g_hst_h[lyr], g_hst_l[lyr], HID, g_w[lyr], HID, n0, 16);
                #pragma unroll
                for (int nf = 0; nf < 4; nf++) {
                    #pragma unroll
                    for (int i = 0; i < aH4[nf].num_elements; i++) aH4[nf].x[i] += aL4[nf].x[i];
                    wmma::store_matrix_sync(
                        &g_gate[lyr][(wm * 16) * G4 + n0 + wn * 64 + nf * 16],
                        aH4[nf], G4, wmma::mem_row_major);
                }
            } else if (blk < 102) {
                dec_run(t - 1);
            }
        }
        gbar(++gen);

        // ---- Ph2: cell0 (po x-GEMM only on non-teacher-forced steps)
        if (!cond) {
            run_gemm<1>(a1H, a1L, sAh, sAl, sB, tid, wm, wn,
                        g_po_h, g_po_l, KX, g_wx0, KX, n0c, 3);
            #pragma unroll
            for (int i = 0; i < a1H[0].num_elements; i++) a1H[0].x[i] += a1L[0].x[i];
            wmma::store_matrix_sync(&cs[wm * 16][wn * 16], a1H[0], 32, wmma::mem_row_major);
            __syncthreads();
            cell(0, true, nullptr);
        } else {
            int ci = (t / 10) * 5 + (t % 10);
            cell(0, false, g_gx[ci]);
        }
        gbar(++gen);

        // ---- Ph3: h0 -> layer1 gates + cell1
        run_gemm<1>(a1H, a1L, sAh, sAl, sB, tid, wm, wn,
                    g_hst_h[0], g_hst_l[0], HID, g_w[3], HID, n0c, 16);
        #pragma unroll
        for (int i = 0; i < a1H[0].num_elements; i++) a1H[0].x[i] += a1L[0].x[i];
        wmma::store_matrix_sync(&cs[wm * 16][wn * 16], a1H[0], 32, wmma::mem_row_major);
        __syncthreads();
        cell(1, true, nullptr);
        gbar(++gen);

        // ---- Ph4: h1 -> layer2 gates + cell2
        run_gemm<1>(a1H, a1L, sAh, sAl, sB, tid, wm, wn,
                    g_hst_h[1], g_hst_l[1], HID, g_w[4], HID, n0c, 16);
        #pragma unroll
        for (int i = 0; i < a1H[0].num_elements; i++) a1H[0].x[i] += a1L[0].x[i];
        wmma::store_matrix_sync(&cs[wm * 16][wn * 16], a1H[0], 32, wmma::mem_row_major);
        __syncthreads();
        cell(2, true, nullptr);
        gbar(++gen);
    }

    // ---- final decoder for t = 99
    if (blk >= 96 && blk < 102) dec_run(TT - 1);
}

// ---------------- launch ----------------
extern "C" void kernel_launch(void* const* d_in, const int* in_sizes, int n_in,
                              void* d_out, int out_size) {
    const float* rs    = (const float*)d_in[0];
    const float* wih1  = (const float*)d_in[1];
    const float* whh1  = (const float*)d_in[2];
    const float* bih1  = (const float*)d_in[3];
    const float* bhh1  = (const float*)d_in[4];
    const float* wih2  = (const float*)d_in[5];
    const float* whh2  = (const float*)d_in[6];
    const float* bih2  = (const float*)d_in[7];
    const float* bhh2  = (const float*)d_in[8];
    const float* wih3  = (const float*)d_in[9];
    const float* whh3  = (const float*)d_in[10];
    const float* bih3  = (const float*)d_in[11];
    const float* bhh3  = (const float*)d_in[12];
    const float* decw  = (const float*)d_in[13];
    const float* decb  = (const float*)d_in[14];
    float* out = (float*)d_out;

    cudaFuncSetAttribute(persist, cudaFuncAttributeMaxDynamicSharedMemorySize, SMEM_BYTES);
    cudaFuncSetAttribute(prep_gx, cudaFuncAttributeMaxDynamicSharedMemorySize, SMEM_BYTES);

    prep_wh<<<2048, 256>>>(whh1, 0);
    prep_wh<<<2048, 256>>>(whh2, 1);
    prep_wh<<<2048, 256>>>(whh3, 2);
    prep_wh<<<2048, 256>>>(wih2, 3);
    prep_wh<<<2048, 256>>>(wih3, 4);
    prep_wx0<<<512, 256>>>(wih1);
    prep_dec<<<256, 256>>>(decw);
    prep_bias<<<16, 256>>>(bih1, bhh1, 0);
    prep_bias<<<16, 256>>>(bih2, bhh2, 1);
    prep_bias<<<16, 256>>>(bih3, bhh3, 2);
    prep_dbias<<<1, 256>>>(decb);
    prep_frames<<<1024, 256>>>(rs);
    prep_zero<<<512, 256>>>();

    dim3 gxg(32, NCOND);
    prep_gx<<<gxg, 256, SMEM_BYTES>>>();

    persist<<<NB, 256, SMEM_BYTES>>>(out);
}